// round 12
// baseline (speedup 1.0000x reference)
#include <cuda_runtime.h>

// LIF membrane update with Blackwell 256-bit vector memory ops:
//   mem_t = (mem_{t-1} - spike_{t-1} * 0.5) * 0.25 + x_t
//   spike_t = rint(clamp(mem_t, 0, 1))   (round-half-to-even, matches jnp.round)
// x: [T=4, N] fp32, out: [T=4, N] fp32.
//
// R12: each thread owns 8 contiguous floats (32B/lane); ld/st.global.v8.f32
// (sm_100+ LDG.E.256/STG.E.256) — warp instr = 1024B DENSE (unlike R2's
// gappy 2x128b, which half-filled sectors and regressed). Halves memory
// instruction count + L1tex request bookkeeping at identical byte traffic.
// N = 8,388,608 floats/plane (divisible by 8); cudaMalloc base + plane
// offsets (33.5 MB) are 32B-aligned.

#define DECAY 0.25f
#define T_STEPS 4

__device__ __forceinline__ void ldg_v8(const float* __restrict__ p, float* v) {
    asm volatile("ld.global.v8.f32 {%0,%1,%2,%3,%4,%5,%6,%7}, [%8];"
                 : "=f"(v[0]), "=f"(v[1]), "=f"(v[2]), "=f"(v[3]),
                   "=f"(v[4]), "=f"(v[5]), "=f"(v[6]), "=f"(v[7])
                 : "l"(p));
}

__device__ __forceinline__ void stg_v8(float* __restrict__ p, const float* v) {
    asm volatile("st.global.v8.f32 [%0], {%1,%2,%3,%4,%5,%6,%7,%8};"
                 :: "l"(p),
                    "f"(v[0]), "f"(v[1]), "f"(v[2]), "f"(v[3]),
                    "f"(v[4]), "f"(v[5]), "f"(v[6]), "f"(v[7])
                 : "memory");
}

__global__ __launch_bounds__(256) void lif_kernel(const float* __restrict__ x,
                                                  float* __restrict__ out,
                                                  int n8, int n_plane) {
    int i = blockIdx.x * blockDim.x + threadIdx.x;
    if (i >= n8) return;

    size_t base = (size_t)i * 8;

    float mem[8], spk[8];
#pragma unroll
    for (int k = 0; k < 8; k++) { mem[k] = 0.f; spk[k] = 0.f; }

#pragma unroll
    for (int t = 0; t < T_STEPS; t++) {
        float xi[8];
        ldg_v8(x + (size_t)t * n_plane + base, xi);

#pragma unroll
        for (int k = 0; k < 8; k++) {
            mem[k] = fmaf(mem[k] - spk[k] * 0.5f, DECAY, xi[k]);
            spk[k] = rintf(fminf(fmaxf(mem[k], 0.f), 1.f));
        }

        stg_v8(out + (size_t)t * n_plane + base, spk);
    }
}

extern "C" void kernel_launch(void* const* d_in, const int* in_sizes, int n_in,
                              void* d_out, int out_size) {
    const float* x = (const float*)d_in[0];
    float* out = (float*)d_out;

    int n_total = in_sizes[0];          // T * N
    int n_plane = n_total / T_STEPS;    // floats per timestep (8,388,608)
    int n8 = n_plane / 8;               // v8 elements per timestep

    int threads = 256;
    int blocks = (n8 + threads - 1) / threads;
    lif_kernel<<<blocks, threads>>>(x, out, n8, n_plane);
}

// round 13
// speedup vs baseline: 1.0426x; 1.0426x over previous
#include <cuda_runtime.h>

// LIF membrane update (FINAL — measured chip roofline):
//   mem_t = (mem_{t-1} - spike_{t-1} * 0.5) * 0.25 + x_t
//   spike_t = rint(clamp(mem_t, 0, 1))   (round-half-to-even, matches jnp.round)
// x: [T=4, N] fp32, out: [T=4, N] fp32, per-element recurrence over t,
// fully fused into one pass (traffic floor: 268.4 MB, zero reuse).
//
// Complete lever sweep (R1-R12), all falsified against this layout:
//   ILP=2 strided 64.8% / ILP=2 coalesced 72.7% / phase-split+ldcs/stcs
//   73.9% / block=512 75.6% / persistent 1-wave 71.3% / v8 LDG.E.256 74.0%
//   vs this kernel's identical-source band 73.4-76.2% DRAM, 35.4-36.8us.
// Bandwidth (5.8-6.0 TB/s) is invariant to access pattern, cache policy,
// launch shape, AND instruction width => path-independent LTS byte-path
// cap (B300_MICROARCH). Traffic is at the information floor. Compute idle.
// This naive one-float4-per-thread kernel is the optimum.

#define DECAY 0.25f
#define T_STEPS 4

__global__ __launch_bounds__(256) void lif_kernel(const float4* __restrict__ x,
                                                  float4* __restrict__ out,
                                                  int n4) {
    int i = blockIdx.x * blockDim.x + threadIdx.x;
    if (i >= n4) return;

    float4 mem = make_float4(0.f, 0.f, 0.f, 0.f);
    float4 spk = make_float4(0.f, 0.f, 0.f, 0.f);

#pragma unroll
    for (int t = 0; t < T_STEPS; t++) {
        float4 xi = x[(size_t)t * n4 + i];

        mem.x = fmaf(mem.x - spk.x * 0.5f, DECAY, xi.x);
        mem.y = fmaf(mem.y - spk.y * 0.5f, DECAY, xi.y);
        mem.z = fmaf(mem.z - spk.z * 0.5f, DECAY, xi.z);
        mem.w = fmaf(mem.w - spk.w * 0.5f, DECAY, xi.w);

        spk.x = rintf(fminf(fmaxf(mem.x, 0.f), 1.f));
        spk.y = rintf(fminf(fmaxf(mem.y, 0.f), 1.f));
        spk.z = rintf(fminf(fmaxf(mem.z, 0.f), 1.f));
        spk.w = rintf(fminf(fmaxf(mem.w, 0.f), 1.f));

        out[(size_t)t * n4 + i] = spk;
    }
}

extern "C" void kernel_launch(void* const* d_in, const int* in_sizes, int n_in,
                              void* d_out, int out_size) {
    const float4* x = (const float4*)d_in[0];
    float4* out = (float4*)d_out;

    int n_total = in_sizes[0];        // T * N
    int n4 = (n_total / T_STEPS) / 4; // float4 elements per timestep

    int threads = 256;
    int blocks = (n4 + threads - 1) / threads;
    lif_kernel<<<blocks, threads>>>(x, out, n4);
}